// round 1
// baseline (speedup 1.0000x reference)
#include <cuda_runtime.h>

// Problem constants
#define BB   8
#define TT   2048
#define DD   1024
#define HH   64
#define MTOT (BB * TT)   // 16384

// Scratch for Q, K, V: 3 * 16384 * 64 floats = 12 MB (static device array: allowed)
__device__ float g_qkv[3ull * MTOT * HH];

// ---------------------------------------------------------------------------
// Kernel 1: fused QKV projection.  C[w] = X[16384,1024] @ W[w][1024,64]
// BM=128, BN=64, BK=16, 256 threads, 8x4 per-thread register tile.
// grid = (MTOT/128, 3)  — grid.y selects Wq/Wk/Wv.
// ---------------------------------------------------------------------------
__global__ __launch_bounds__(256) void qkv_kernel(
    const float* __restrict__ X,
    const float* __restrict__ Wq,
    const float* __restrict__ Wk,
    const float* __restrict__ Wv)
{
    __shared__ float Xs[128 * 20];   // [m][k], row stride 20 (pad for banks, f4-aligned)
    __shared__ float Ws[16 * 64];    // [k][n]

    const float* W = (blockIdx.y == 0) ? Wq : ((blockIdx.y == 1) ? Wk : Wv);
    float* C = g_qkv + (size_t)blockIdx.y * MTOT * HH;

    const int m0   = blockIdx.x * 128;
    const int tid  = threadIdx.x;
    const int trow = tid >> 4;   // 0..15  -> rows trow*8 .. +7
    const int tcol = tid & 15;   // 0..15  -> cols tcol*4 .. +3

    float acc[8][4];
#pragma unroll
    for (int i = 0; i < 8; i++) {
        acc[i][0] = 0.f; acc[i][1] = 0.f; acc[i][2] = 0.f; acc[i][3] = 0.f;
    }

    for (int kt = 0; kt < DD / 16; kt++) {
        // Load X tile 128x16 (512 float4, 2 per thread)
#pragma unroll
        for (int i = 0; i < 2; i++) {
            int f  = tid + 256 * i;
            int m  = f >> 2;
            int kq = f & 3;
            float4 v = *(const float4*)(X + (size_t)(m0 + m) * DD + kt * 16 + kq * 4);
            *(float4*)(Xs + m * 20 + kq * 4) = v;
        }
        // Load W tile 16x64 (256 float4, 1 per thread) — coalesced
        {
            int r  = tid >> 4;
            int c4 = tid & 15;
            *(float4*)(Ws + r * 64 + c4 * 4) =
                *(const float4*)(W + (size_t)(kt * 16 + r) * HH + c4 * 4);
        }
        __syncthreads();

#pragma unroll
        for (int k = 0; k < 16; k++) {
            float4 b4 = *(const float4*)(Ws + k * 64 + tcol * 4);
#pragma unroll
            for (int i = 0; i < 8; i++) {
                float a = Xs[(trow * 8 + i) * 20 + k];   // broadcast within warp
                acc[i][0] = fmaf(a, b4.x, acc[i][0]);
                acc[i][1] = fmaf(a, b4.y, acc[i][1]);
                acc[i][2] = fmaf(a, b4.z, acc[i][2]);
                acc[i][3] = fmaf(a, b4.w, acc[i][3]);
            }
        }
        __syncthreads();
    }

#pragma unroll
    for (int i = 0; i < 8; i++) {
        float4 v = make_float4(acc[i][0], acc[i][1], acc[i][2], acc[i][3]);
        *(float4*)(C + (size_t)(m0 + trow * 8 + i) * HH + tcol * 4) = v;
    }
}

// ---------------------------------------------------------------------------
// Kernel 2: flash attention (causal), q-tile=64, kv-tile=64.
// Block g handles q-tiles {g, 31-g}: exactly 33 kv-tile iterations per block.
// grid = (16, 8), 256 threads, dynamic smem ~68 KB.
// ---------------------------------------------------------------------------
#define QSTR 68
#define KSTR 65
#define PSTR 65

__global__ __launch_bounds__(256) void attn_kernel(float* __restrict__ Out)
{
    extern __shared__ float sm[];
    float* Qs    = sm;                    // 64 * 68
    float* Ks    = Qs + 64 * QSTR;        // 64 * 65
    float* Ps    = Ks + 64 * KSTR;        // 64 * 65
    float* Vs    = Ps + 64 * PSTR;        // 64 * 64 (float4-accessed)
    float* row_m = Vs + 64 * 64;          // 64
    float* row_l = row_m + 64;            // 64
    float* row_a = row_l + 64;            // 64

    const int b = blockIdx.y;
    const int g = blockIdx.x;

    const float* Qg = g_qkv + (size_t)b * TT * HH;
    const float* Kg = g_qkv + (size_t)MTOT * HH + (size_t)b * TT * HH;
    const float* Vg = g_qkv + 2ull * MTOT * HH + (size_t)b * TT * HH;

    const int tid  = threadIdx.x;
    // S-phase mapping: 16x16 thread grid, each thread a 4x4 tile of S
    const int sr = tid >> 4;     // 0..15
    const int sc = tid & 15;     // 0..15
    // O-phase mapping: 64 rows x 4 column groups of 16
    const int orow = tid >> 2;   // 0..63
    const int ocg  = tid & 3;    // 0..3

    for (int pi = 0; pi < 2; pi++) {
        const int qt = pi ? (31 - g) : g;
        const int q0 = qt * 64;

        // Load Q tile (64x64, float4)
#pragma unroll
        for (int i = 0; i < 4; i++) {
            int f = tid + 256 * i;
            int r = f >> 4, c4 = f & 15;
            *(float4*)(Qs + r * QSTR + c4 * 4) =
                *(const float4*)(Qg + (size_t)(q0 + r) * HH + c4 * 4);
        }
        if (tid < 64) { row_m[tid] = -1e30f; row_l[tid] = 0.f; }

        float o[4][4];
#pragma unroll
        for (int v4 = 0; v4 < 4; v4++) {
            o[v4][0] = 0.f; o[v4][1] = 0.f; o[v4][2] = 0.f; o[v4][3] = 0.f;
        }
        __syncthreads();

        for (int kt = 0; kt <= qt; kt++) {
            const int k0 = kt * 64;
            // Load K (scalar STS, pad-65) and V (float4) tiles
#pragma unroll
            for (int i = 0; i < 4; i++) {
                int f = tid + 256 * i;
                int r = f >> 4, c4 = f & 15;
                float4 kv = *(const float4*)(Kg + (size_t)(k0 + r) * HH + c4 * 4);
                float* d = Ks + r * KSTR + c4 * 4;
                d[0] = kv.x; d[1] = kv.y; d[2] = kv.z; d[3] = kv.w;
                *(float4*)(Vs + r * 64 + c4 * 4) =
                    *(const float4*)(Vg + (size_t)(k0 + r) * HH + c4 * 4);
            }
            __syncthreads();

            // ---- S = Q @ K^T (4x4 per thread) ----
            float s4[4][4];
#pragma unroll
            for (int i = 0; i < 4; i++) {
                s4[i][0] = 0.f; s4[i][1] = 0.f; s4[i][2] = 0.f; s4[i][3] = 0.f;
            }
#pragma unroll 8
            for (int h = 0; h < HH; h++) {
                float qa[4], kb[4];
#pragma unroll
                for (int i = 0; i < 4; i++) qa[i] = Qs[(sr * 4 + i) * QSTR + h];
#pragma unroll
                for (int j = 0; j < 4; j++) kb[j] = Ks[(sc * 4 + j) * KSTR + h];
#pragma unroll
                for (int i = 0; i < 4; i++)
#pragma unroll
                    for (int j = 0; j < 4; j++)
                        s4[i][j] = fmaf(qa[i], kb[j], s4[i][j]);
            }

            // ---- scale + causal mask + online softmax ----
            const float scale = 0.125f;   // 1/sqrt(64)
            const bool diag = (kt == qt);
            float mt[4];
#pragma unroll
            for (int i = 0; i < 4; i++) {
#pragma unroll
                for (int j = 0; j < 4; j++) {
                    float v = s4[i][j] * scale;
                    if (diag && (sc * 4 + j) > (sr * 4 + i)) v = -1e30f;
                    s4[i][j] = v;
                }
                mt[i] = fmaxf(fmaxf(s4[i][0], s4[i][1]), fmaxf(s4[i][2], s4[i][3]));
            }
            // reduce max across the 16 lanes sharing these rows (stays in half-warp)
#pragma unroll
            for (int off = 1; off < 16; off <<= 1)
#pragma unroll
                for (int i = 0; i < 4; i++)
                    mt[i] = fmaxf(mt[i], __shfl_xor_sync(0xffffffffu, mt[i], off));

            float mold[4], mnew[4], ts[4];
#pragma unroll
            for (int i = 0; i < 4; i++) {
                mold[i] = row_m[sr * 4 + i];
                mnew[i] = fmaxf(mold[i], mt[i]);
                float t = 0.f;
#pragma unroll
                for (int j = 0; j < 4; j++) {
                    s4[i][j] = __expf(s4[i][j] - mnew[i]);
                    t += s4[i][j];
                }
                ts[i] = t;
            }
#pragma unroll
            for (int off = 1; off < 16; off <<= 1)
#pragma unroll
                for (int i = 0; i < 4; i++)
                    ts[i] += __shfl_xor_sync(0xffffffffu, ts[i], off);

            if (sc == 0) {
#pragma unroll
                for (int i = 0; i < 4; i++) {
                    float a = __expf(mold[i] - mnew[i]);
                    row_a[sr * 4 + i] = a;
                    row_m[sr * 4 + i] = mnew[i];
                    row_l[sr * 4 + i] = row_l[sr * 4 + i] * a + ts[i];
                }
            }
            // publish P
#pragma unroll
            for (int i = 0; i < 4; i++)
#pragma unroll
                for (int j = 0; j < 4; j++)
                    Ps[(sr * 4 + i) * PSTR + sc * 4 + j] = s4[i][j];
            __syncthreads();

            // ---- O = O*alpha + P @ V (O-phase mapping) ----
            float a = row_a[orow];
#pragma unroll
            for (int v4 = 0; v4 < 4; v4++) {
                o[v4][0] *= a; o[v4][1] *= a; o[v4][2] *= a; o[v4][3] *= a;
            }
#pragma unroll 8
            for (int j = 0; j < 64; j++) {
                float p = Ps[orow * PSTR + j];   // broadcast
#pragma unroll
                for (int v4 = 0; v4 < 4; v4++) {
                    float4 vv = *(const float4*)(Vs + j * 64 + ocg * 16 + v4 * 4);
                    o[v4][0] = fmaf(p, vv.x, o[v4][0]);
                    o[v4][1] = fmaf(p, vv.y, o[v4][1]);
                    o[v4][2] = fmaf(p, vv.z, o[v4][2]);
                    o[v4][3] = fmaf(p, vv.w, o[v4][3]);
                }
            }
            __syncthreads();   // protect Ks/Vs/Ps/row_* for next iteration
        }

        // epilogue: normalize and store
        float linv = 1.0f / row_l[orow];
#pragma unroll
        for (int v4 = 0; v4 < 4; v4++) {
            float4 v = make_float4(o[v4][0] * linv, o[v4][1] * linv,
                                   o[v4][2] * linv, o[v4][3] * linv);
            *(float4*)(Out + ((size_t)b * TT + q0 + orow) * HH + ocg * 16 + v4 * 4) = v;
        }
        __syncthreads();   // smem reuse across pi iterations
    }
}

// ---------------------------------------------------------------------------
extern "C" void kernel_launch(void* const* d_in, const int* in_sizes, int n_in,
                              void* d_out, int out_size)
{
    const float* x  = (const float*)d_in[0];
    const float* Wq = (const float*)d_in[1];
    const float* Wk = (const float*)d_in[2];
    const float* Wv = (const float*)d_in[3];
    float* out = (float*)d_out;

    const size_t smem_bytes =
        (size_t)(64 * QSTR + 64 * KSTR + 64 * PSTR + 64 * 64 + 3 * 64) * sizeof(float);
    cudaFuncSetAttribute(attn_kernel, cudaFuncAttributeMaxDynamicSharedMemorySize,
                         (int)smem_bytes);

    qkv_kernel<<<dim3(MTOT / 128, 3), 256>>>(x, Wq, Wk, Wv);
    attn_kernel<<<dim3(16, BB), 256, smem_bytes>>>(out);
}

// round 2
// speedup vs baseline: 1.5145x; 1.5145x over previous
#include <cuda_runtime.h>

// Problem constants
#define BB   8
#define TT   2048
#define DD   1024
#define HH   64
#define MTOT (BB * TT)   // 16384

// Scratch for Q, K, V: 3 * 16384 * 64 floats = 12 MB
__device__ float g_qkv[3ull * MTOT * HH];

// ---------------------------------------------------------------------------
// Kernel 1: fused QKV projection.  C[w] = X[16384,1024] @ W[w][1024,64]
// (unchanged — measured at the FFMA roofline)
// ---------------------------------------------------------------------------
__global__ __launch_bounds__(256) void qkv_kernel(
    const float* __restrict__ X,
    const float* __restrict__ Wq,
    const float* __restrict__ Wk,
    const float* __restrict__ Wv)
{
    __shared__ float Xs[128 * 20];
    __shared__ float Ws[16 * 64];

    const float* W = (blockIdx.y == 0) ? Wq : ((blockIdx.y == 1) ? Wk : Wv);
    float* C = g_qkv + (size_t)blockIdx.y * MTOT * HH;

    const int m0   = blockIdx.x * 128;
    const int tid  = threadIdx.x;
    const int trow = tid >> 4;
    const int tcol = tid & 15;

    float acc[8][4];
#pragma unroll
    for (int i = 0; i < 8; i++) {
        acc[i][0] = 0.f; acc[i][1] = 0.f; acc[i][2] = 0.f; acc[i][3] = 0.f;
    }

    for (int kt = 0; kt < DD / 16; kt++) {
#pragma unroll
        for (int i = 0; i < 2; i++) {
            int f  = tid + 256 * i;
            int m  = f >> 2;
            int kq = f & 3;
            float4 v = *(const float4*)(X + (size_t)(m0 + m) * DD + kt * 16 + kq * 4);
            *(float4*)(Xs + m * 20 + kq * 4) = v;
        }
        {
            int r  = tid >> 4;
            int c4 = tid & 15;
            *(float4*)(Ws + r * 64 + c4 * 4) =
                *(const float4*)(W + (size_t)(kt * 16 + r) * HH + c4 * 4);
        }
        __syncthreads();

#pragma unroll
        for (int k = 0; k < 16; k++) {
            float4 b4 = *(const float4*)(Ws + k * 64 + tcol * 4);
#pragma unroll
            for (int i = 0; i < 8; i++) {
                float a = Xs[(trow * 8 + i) * 20 + k];
                acc[i][0] = fmaf(a, b4.x, acc[i][0]);
                acc[i][1] = fmaf(a, b4.y, acc[i][1]);
                acc[i][2] = fmaf(a, b4.z, acc[i][2]);
                acc[i][3] = fmaf(a, b4.w, acc[i][3]);
            }
        }
        __syncthreads();
    }

#pragma unroll
    for (int i = 0; i < 8; i++) {
        float4 v = make_float4(acc[i][0], acc[i][1], acc[i][2], acc[i][3]);
        *(float4*)(C + (size_t)(m0 + trow * 8 + i) * HH + tcol * 4) = v;
    }
}

// ---------------------------------------------------------------------------
// Kernel 2: flash attention (causal), q-tile=64, kv-tile=64.
// Block g handles q-tiles {g, 31-g}: exactly 33 kv-iterations per block.
// Unified 16x16 thread map (4x4 per-thread tiles for S AND PV).
// Row stats in registers (consistent across the 16-lane row group via shfl).
// grid = (16, 8), 256 threads, ~70KB dynamic smem.
// ---------------------------------------------------------------------------
#define QSTR4 17     // Q row stride in float4 (68 floats, odd f4 -> conflict-free)
#define KSTR4 17     // K row stride in float4
#define PSTR  80     // P row stride in floats (80 mod 32 == 16: no cross-half conflict)
#define VSTR4 16     // V row stride in float4 (64 floats)

__global__ __launch_bounds__(256) void attn_kernel(float* __restrict__ Out)
{
    extern __shared__ float sm[];
    float4* Qs = (float4*)sm;                       // 64 * 17 f4
    float4* Ks = Qs + 64 * QSTR4;                   // 64 * 17 f4
    float*  Ps = (float*)(Ks + 64 * KSTR4);         // 64 * 80 f
    float4* Vs = (float4*)(Ps + 64 * PSTR);         // 64 * 16 f4

    const int b = blockIdx.y;
    const int g = blockIdx.x;

    const float* Qg = g_qkv + (size_t)b * TT * HH;
    const float* Kg = g_qkv + (size_t)MTOT * HH + (size_t)b * TT * HH;
    const float* Vg = g_qkv + 2ull * MTOT * HH + (size_t)b * TT * HH;

    const int tid = threadIdx.x;
    const int sr  = tid >> 4;    // 0..15 : rows sr*4 .. sr*4+3
    const int sc  = tid & 15;    // 0..15 : k-cols {sc, sc+16, sc+32, sc+48}, h-cols sc*4..+3

    for (int pi = 0; pi < 2; pi++) {
        const int qt = pi ? (31 - g) : g;
        const int q0 = qt * 64;

        // Load Q tile (64x64, float4, conflict-free stores)
#pragma unroll
        for (int i = 0; i < 4; i++) {
            int f = tid + 256 * i;
            int r = f >> 4, c4 = f & 15;
            Qs[r * QSTR4 + c4] = ((const float4*)(Qg + (size_t)(q0 + r) * HH))[c4];
        }

        float m[4], l[4], o[4][4];
#pragma unroll
        for (int i = 0; i < 4; i++) {
            m[i] = -1e30f; l[i] = 0.f;
            o[i][0] = 0.f; o[i][1] = 0.f; o[i][2] = 0.f; o[i][3] = 0.f;
        }
        __syncthreads();

        for (int kt = 0; kt <= qt; kt++) {
            const int k0 = kt * 64;
            // Load K, V tiles
#pragma unroll
            for (int i = 0; i < 4; i++) {
                int f = tid + 256 * i;
                int r = f >> 4, c4 = f & 15;
                Ks[r * KSTR4 + c4] = ((const float4*)(Kg + (size_t)(k0 + r) * HH))[c4];
                Vs[r * VSTR4 + c4] = ((const float4*)(Vg + (size_t)(k0 + r) * HH))[c4];
            }
            __syncthreads();

            // ---- S = Q @ K^T : 4x4 per thread, float4 over h ----
            float s4[4][4];
#pragma unroll
            for (int i = 0; i < 4; i++) {
                s4[i][0] = 0.f; s4[i][1] = 0.f; s4[i][2] = 0.f; s4[i][3] = 0.f;
            }
#pragma unroll 4
            for (int hq = 0; hq < 16; hq++) {
                float4 qa[4], kb[4];
#pragma unroll
                for (int i = 0; i < 4; i++) qa[i] = Qs[(sr * 4 + i) * QSTR4 + hq];
#pragma unroll
                for (int j = 0; j < 4; j++) kb[j] = Ks[(sc + 16 * j) * KSTR4 + hq];
#pragma unroll
                for (int i = 0; i < 4; i++)
#pragma unroll
                    for (int j = 0; j < 4; j++) {
                        s4[i][j] = fmaf(qa[i].x, kb[j].x, s4[i][j]);
                        s4[i][j] = fmaf(qa[i].y, kb[j].y, s4[i][j]);
                        s4[i][j] = fmaf(qa[i].z, kb[j].z, s4[i][j]);
                        s4[i][j] = fmaf(qa[i].w, kb[j].w, s4[i][j]);
                    }
            }

            // ---- scale + causal mask + online softmax (registers + shfl) ----
            const float scale = 0.125f;   // 1/sqrt(64)
            const bool diag = (kt == qt);
            float mt[4];
#pragma unroll
            for (int i = 0; i < 4; i++) {
#pragma unroll
                for (int j = 0; j < 4; j++) {
                    float v = s4[i][j] * scale;
                    if (diag && (sc + 16 * j) > (sr * 4 + i)) v = -1e30f;
                    s4[i][j] = v;
                }
                mt[i] = fmaxf(fmaxf(s4[i][0], s4[i][1]), fmaxf(s4[i][2], s4[i][3]));
            }
#pragma unroll
            for (int off = 1; off < 16; off <<= 1)
#pragma unroll
                for (int i = 0; i < 4; i++)
                    mt[i] = fmaxf(mt[i], __shfl_xor_sync(0xffffffffu, mt[i], off));

            float alpha[4], ts[4];
#pragma unroll
            for (int i = 0; i < 4; i++) {
                float mnew = fmaxf(m[i], mt[i]);
                alpha[i] = __expf(m[i] - mnew);
                m[i] = mnew;
                float t = 0.f;
#pragma unroll
                for (int j = 0; j < 4; j++) {
                    s4[i][j] = __expf(s4[i][j] - mnew);
                    t += s4[i][j];
                }
                ts[i] = t;
            }
#pragma unroll
            for (int off = 1; off < 16; off <<= 1)
#pragma unroll
                for (int i = 0; i < 4; i++)
                    ts[i] += __shfl_xor_sync(0xffffffffu, ts[i], off);
#pragma unroll
            for (int i = 0; i < 4; i++)
                l[i] = l[i] * alpha[i] + ts[i];

            // publish P (col index = actual k position sc+16j)
#pragma unroll
            for (int i = 0; i < 4; i++)
#pragma unroll
                for (int j = 0; j < 4; j++)
                    Ps[(sr * 4 + i) * PSTR + sc + 16 * j] = s4[i][j];
            __syncthreads();

            // ---- O = O*alpha + P @ V : same 4x4 mapping ----
#pragma unroll
            for (int i = 0; i < 4; i++) {
                o[i][0] *= alpha[i]; o[i][1] *= alpha[i];
                o[i][2] *= alpha[i]; o[i][3] *= alpha[i];
            }
#pragma unroll 4
            for (int j = 0; j < 64; j++) {
                float p[4];
#pragma unroll
                for (int i = 0; i < 4; i++) p[i] = Ps[(sr * 4 + i) * PSTR + j]; // broadcast
                float4 v = Vs[j * VSTR4 + sc];   // conflict-free
#pragma unroll
                for (int i = 0; i < 4; i++) {
                    o[i][0] = fmaf(p[i], v.x, o[i][0]);
                    o[i][1] = fmaf(p[i], v.y, o[i][1]);
                    o[i][2] = fmaf(p[i], v.z, o[i][2]);
                    o[i][3] = fmaf(p[i], v.w, o[i][3]);
                }
            }
            __syncthreads();   // protect Ks/Vs/Ps for next iteration
        }

        // epilogue: normalize and store (coalesced float4)
#pragma unroll
        for (int i = 0; i < 4; i++) {
            float linv = 1.0f / l[i];
            float4 v = make_float4(o[i][0] * linv, o[i][1] * linv,
                                   o[i][2] * linv, o[i][3] * linv);
            ((float4*)(Out + ((size_t)b * TT + q0 + sr * 4 + i) * HH))[sc] = v;
        }
        __syncthreads();   // smem reuse across pi iterations
    }
}

// ---------------------------------------------------------------------------
extern "C" void kernel_launch(void* const* d_in, const int* in_sizes, int n_in,
                              void* d_out, int out_size)
{
    const float* x  = (const float*)d_in[0];
    const float* Wq = (const float*)d_in[1];
    const float* Wk = (const float*)d_in[2];
    const float* Wv = (const float*)d_in[3];
    float* out = (float*)d_out;

    const size_t smem_bytes =
        (size_t)(64 * QSTR4 * 4 + 64 * KSTR4 * 4 + 64 * PSTR + 64 * VSTR4 * 4)
        * sizeof(float);
    cudaFuncSetAttribute(attn_kernel, cudaFuncAttributeMaxDynamicSharedMemorySize,
                         (int)smem_bytes);

    qkv_kernel<<<dim3(MTOT / 128, 3), 256>>>(x, Wq, Wk, Wv);
    attn_kernel<<<dim3(16, BB), 256, smem_bytes>>>(out);
}

// round 4
// speedup vs baseline: 2.1451x; 1.4164x over previous
#include <cuda_runtime.h>
#include <cuda_bf16.h>
#include <cstdint>

// Problem constants
#define BB   8
#define TT   2048
#define DD   1024
#define HH   64
#define MTOT (BB * TT)   // 16384

// Scratch: Q,K,V fp32 (12MB) + split-precision transposed weights (768KB)
__device__ float g_qkv[3ull * MTOT * HH];
__device__ __nv_bfloat16 g_WtH[192 * 1024];
__device__ __nv_bfloat16 g_WtL[192 * 1024];

// ===========================================================================
// Helpers (plain sm_100-compatible: mma.sync + cp.async only)
// ===========================================================================
__device__ __forceinline__ uint32_t smem_u32(const void* p) {
    uint32_t a;
    asm("{ .reg .u64 t; cvta.to.shared.u64 t, %1; cvt.u32.u64 %0, t; }"
        : "=r"(a) : "l"(p));
    return a;
}
#define CP_ASYNC16(dst, src) \
    asm volatile("cp.async.cg.shared.global [%0], [%1], 16;" \
                 :: "r"(dst), "l"(src) : "memory")
#define CP_COMMIT() asm volatile("cp.async.commit_group;" ::: "memory")
#define CP_WAIT1()  asm volatile("cp.async.wait_group 1;" ::: "memory")
#define CP_WAIT0()  asm volatile("cp.async.wait_group 0;" ::: "memory")

// split one float2 into packed bf16x2 hi and residual-lo fragments
__device__ __forceinline__ void split2(float2 f, uint32_t& hi, uint32_t& lo) {
    uint32_t h;
    asm("cvt.rn.bf16x2.f32 %0, %1, %2;" : "=r"(h) : "f"(f.y), "f"(f.x));
    float hf0 = __uint_as_float(h << 16);
    float hf1 = __uint_as_float(h & 0xffff0000u);
    float l0 = f.x - hf0;
    float l1 = f.y - hf1;
    asm("cvt.rn.bf16x2.f32 %0, %1, %2;" : "=r"(lo) : "f"(l1), "f"(l0));
    hi = h;
}

__device__ __forceinline__ void mma16816(float* c, const uint32_t* a, uint2 b) {
    asm volatile(
        "mma.sync.aligned.m16n8k16.row.col.f32.bf16.bf16.f32 "
        "{%0,%1,%2,%3}, {%4,%5,%6,%7}, {%8,%9}, {%0,%1,%2,%3};"
        : "+f"(c[0]), "+f"(c[1]), "+f"(c[2]), "+f"(c[3])
        : "r"(a[0]), "r"(a[1]), "r"(a[2]), "r"(a[3]), "r"(b.x), "r"(b.y));
}

// ===========================================================================
// Kernel 0: W prep. fp32 [1024,64] x3 -> bf16 hi/lo, transposed [192,1024],
// with in-k16 pair permutation so B fragments (b0..b3) are 8B-contiguous:
// within each k16 block, pair p (k=2p,2p+1) stored at element (p&3)*4+(p>>2)*2(+odd).
// ===========================================================================
__global__ __launch_bounds__(256) void wprep_kernel(
    const float* __restrict__ Wq,
    const float* __restrict__ Wk,
    const float* __restrict__ Wv)
{
    const int n = blockIdx.x;                 // 0..191
    const float* W = (n < 64) ? Wq : ((n < 128) ? Wk : Wv);
    const int nn = n & 63;
    for (int k = threadIdx.x; k < 1024; k += 256) {
        float w = W[(size_t)k * 64 + nn];
        __nv_bfloat16 h = __float2bfloat16(w);
        float r = w - __bfloat162float(h);
        int p   = (k & 15) >> 1;
        int pos = (k & ~15) + (p & 3) * 4 + (p >> 2) * 2 + (k & 1);
        g_WtH[(size_t)n * 1024 + pos] = h;
        g_WtL[(size_t)n * 1024 + pos] = __float2bfloat16(r);
    }
}

// ===========================================================================
// Kernel 1: QKV projection via mma.sync bf16 split precision.
// C[g][16384,64] = X @ W[g].  Per CTA: 128 rows x 192 cols.  K chunks of 64,
// cp.async double-buffered.  8 warps = 4(m,32 rows) x 2(n,96 cols).
// X kept fp32 in smem; hi/lo fragments built at load time.
// ===========================================================================
#define XS_STRIDE 272                    // bytes per X row (68 floats)
#define WS_STRIDE 144                    // bytes per W row (64 bf16 + 16B pad)
#define XS_BYTES  (128 * XS_STRIDE)      // 34816
#define WS_BYTES  (192 * WS_STRIDE)      // 27648
#define QS_STAGE  (XS_BYTES + 2 * WS_BYTES)   // 90112
#define QS_TOTAL  (2 * QS_STAGE)              // 180224

__global__ __launch_bounds__(256, 1) void qkv_mma_kernel(const float* __restrict__ X)
{
    extern __shared__ char smem[];
    const uint32_t sb = smem_u32(smem);
    const int tid  = threadIdx.x;
    const int wid  = tid >> 5;
    const int lane = tid & 31;
    const int gid  = lane >> 2;          // 0..7
    const int tq   = lane & 3;           // 0..3
    const int wm   = (wid & 3) * 32;     // row offset within CTA (0,32,64,96)
    const int wn   = (wid >> 2) * 96;    // col offset within 192 (0 or 96)

    const char* Xg = (const char*)(X + (size_t)blockIdx.x * 128 * DD);
    const char* WHg = (const char*)g_WtH;
    const char* WLg = (const char*)g_WtL;

    // async copy of chunk c into stage s
    auto issue = [&](int c, int s) {
        const uint32_t st = sb + s * QS_STAGE;
        const char* xs = Xg + c * 256;                 // 64 floats = 256B
#pragma unroll
        for (int i = 0; i < 8; i++) {
            int u = tid + 256 * i;                     // 2048 16B units
            int r = u >> 4, col = u & 15;
            CP_ASYNC16(st + r * XS_STRIDE + col * 16, xs + (size_t)r * 4096 + col * 16);
        }
        const uint32_t wh = st + XS_BYTES;
        const uint32_t wl = wh + WS_BYTES;
        const char* whs = WHg + c * 128;               // 64 bf16 = 128B
        const char* wls = WLg + c * 128;
#pragma unroll
        for (int i = 0; i < 6; i++) {
            int u = tid + 256 * i;                     // 1536 units per split
            int n = u >> 3, col = u & 7;
            CP_ASYNC16(wh + n * WS_STRIDE + col * 16, whs + (size_t)n * 2048 + col * 16);
            CP_ASYNC16(wl + n * WS_STRIDE + col * 16, wls + (size_t)n * 2048 + col * 16);
        }
        CP_COMMIT();
    };

    float acc[2][12][4];
#pragma unroll
    for (int m = 0; m < 2; m++)
#pragma unroll
        for (int j = 0; j < 12; j++) {
            acc[m][j][0] = 0.f; acc[m][j][1] = 0.f;
            acc[m][j][2] = 0.f; acc[m][j][3] = 0.f;
        }

    issue(0, 0);

    for (int c = 0; c < 16; c++) {
        const int s = c & 1;
        if (c < 15) { issue(c + 1, s ^ 1); CP_WAIT1(); }
        else        { CP_WAIT0(); }
        __syncthreads();

        const char* Xs = smem + s * QS_STAGE;
        const char* Wh = Xs + XS_BYTES;
        const char* Wl = Wh + WS_BYTES;

#pragma unroll
        for (int ks = 0; ks < 4; ks++) {
            // ---- A fragments: load fp32, split to hi/lo bf16x2 ----
            uint32_t Ah[2][4], Al[2][4];
#pragma unroll
            for (int m = 0; m < 2; m++) {
                const int r0 = wm + m * 16 + gid;
                const char* base = Xs + (size_t)r0 * XS_STRIDE + ks * 64 + tq * 8;
                float2 f0 = *(const float2*)(base);
                float2 f1 = *(const float2*)(base + 8 * XS_STRIDE);
                float2 f2 = *(const float2*)(base + 32);
                float2 f3 = *(const float2*)(base + 8 * XS_STRIDE + 32);
                split2(f0, Ah[m][0], Al[m][0]);
                split2(f1, Ah[m][1], Al[m][1]);
                split2(f2, Ah[m][2], Al[m][2]);
                split2(f3, Ah[m][3], Al[m][3]);
            }
            // ---- B fragments + MMAs ----
#pragma unroll
            for (int j = 0; j < 12; j++) {
                const size_t boff = (size_t)(wn + j * 8 + gid) * WS_STRIDE + ks * 32 + tq * 8;
                uint2 bh = *(const uint2*)(Wh + boff);
                uint2 bl = *(const uint2*)(Wl + boff);
#pragma unroll
                for (int m = 0; m < 2; m++) {
                    mma16816(acc[m][j], Ah[m], bh);
                    mma16816(acc[m][j], Ah[m], bl);
                    mma16816(acc[m][j], Al[m], bh);
                }
            }
        }
        __syncthreads();
    }

    // ---- epilogue: write fp32 Q/K/V ----
#pragma unroll
    for (int m = 0; m < 2; m++) {
        const size_t row = (size_t)blockIdx.x * 128 + wm + m * 16 + gid;
#pragma unroll
        for (int j = 0; j < 12; j++) {
            const int nc = wn + j * 8 + tq * 2;
            const int g  = nc >> 6;
            const int cc = nc & 63;
            float* Cg = g_qkv + (size_t)g * MTOT * HH;
            *(float2*)(Cg + row * HH + cc) =
                make_float2(acc[m][j][0], acc[m][j][1]);
            *(float2*)(Cg + (row + 8) * HH + cc) =
                make_float2(acc[m][j][2], acc[m][j][3]);
        }
    }
}

// ---------------------------------------------------------------------------
// Kernel 2: flash attention (causal) — unchanged (known-good, 211us).
// ---------------------------------------------------------------------------
#define QSTR4 17
#define KSTR4 17
#define PSTR  80
#define VSTR4 16

__global__ __launch_bounds__(256) void attn_kernel(float* __restrict__ Out)
{
    extern __shared__ float sm[];
    float4* Qs = (float4*)sm;
    float4* Ks = Qs + 64 * QSTR4;
    float*  Ps = (float*)(Ks + 64 * KSTR4);
    float4* Vs = (float4*)(Ps + 64 * PSTR);

    const int b = blockIdx.y;
    const int g = blockIdx.x;

    const float* Qg = g_qkv + (size_t)b * TT * HH;
    const float* Kg = g_qkv + (size_t)MTOT * HH + (size_t)b * TT * HH;
    const float* Vg = g_qkv + 2ull * MTOT * HH + (size_t)b * TT * HH;

    const int tid = threadIdx.x;
    const int sr  = tid >> 4;
    const int sc  = tid & 15;

    for (int pi = 0; pi < 2; pi++) {
        const int qt = pi ? (31 - g) : g;
        const int q0 = qt * 64;

#pragma unroll
        for (int i = 0; i < 4; i++) {
            int f = tid + 256 * i;
            int r = f >> 4, c4 = f & 15;
            Qs[r * QSTR4 + c4] = ((const float4*)(Qg + (size_t)(q0 + r) * HH))[c4];
        }

        float m[4], l[4], o[4][4];
#pragma unroll
        for (int i = 0; i < 4; i++) {
            m[i] = -1e30f; l[i] = 0.f;
            o[i][0] = 0.f; o[i][1] = 0.f; o[i][2] = 0.f; o[i][3] = 0.f;
        }
        __syncthreads();

        for (int kt = 0; kt <= qt; kt++) {
            const int k0 = kt * 64;
#pragma unroll
            for (int i = 0; i < 4; i++) {
                int f = tid + 256 * i;
                int r = f >> 4, c4 = f & 15;
                Ks[r * KSTR4 + c4] = ((const float4*)(Kg + (size_t)(k0 + r) * HH))[c4];
                Vs[r * VSTR4 + c4] = ((const float4*)(Vg + (size_t)(k0 + r) * HH))[c4];
            }
            __syncthreads();

            float s4[4][4];
#pragma unroll
            for (int i = 0; i < 4; i++) {
                s4[i][0] = 0.f; s4[i][1] = 0.f; s4[i][2] = 0.f; s4[i][3] = 0.f;
            }
#pragma unroll 4
            for (int hq = 0; hq < 16; hq++) {
                float4 qa[4], kb[4];
#pragma unroll
                for (int i = 0; i < 4; i++) qa[i] = Qs[(sr * 4 + i) * QSTR4 + hq];
#pragma unroll
                for (int j = 0; j < 4; j++) kb[j] = Ks[(sc + 16 * j) * KSTR4 + hq];
#pragma unroll
                for (int i = 0; i < 4; i++)
#pragma unroll
                    for (int j = 0; j < 4; j++) {
                        s4[i][j] = fmaf(qa[i].x, kb[j].x, s4[i][j]);
                        s4[i][j] = fmaf(qa[i].y, kb[j].y, s4[i][j]);
                        s4[i][j] = fmaf(qa[i].z, kb[j].z, s4[i][j]);
                        s4[i][j] = fmaf(qa[i].w, kb[j].w, s4[i][j]);
                    }
            }

            const float scale = 0.125f;
            const bool diag = (kt == qt);
            float mt[4];
#pragma unroll
            for (int i = 0; i < 4; i++) {
#pragma unroll
                for (int j = 0; j < 4; j++) {
                    float v = s4[i][j] * scale;
                    if (diag && (sc + 16 * j) > (sr * 4 + i)) v = -1e30f;
                    s4[i][j] = v;
                }
                mt[i] = fmaxf(fmaxf(s4[i][0], s4[i][1]), fmaxf(s4[i][2], s4[i][3]));
            }
#pragma unroll
            for (int off = 1; off < 16; off <<= 1)
#pragma unroll
                for (int i = 0; i < 4; i++)
                    mt[i] = fmaxf(mt[i], __shfl_xor_sync(0xffffffffu, mt[i], off));

            float alpha[4], ts[4];
#pragma unroll
            for (int i = 0; i < 4; i++) {
                float mnew = fmaxf(m[i], mt[i]);
                alpha[i] = __expf(m[i] - mnew);
                m[i] = mnew;
                float t = 0.f;
#pragma unroll
                for (int j = 0; j < 4; j++) {
                    s4[i][j] = __expf(s4[i][j] - mnew);
                    t += s4[i][j];
                }
                ts[i] = t;
            }
#pragma unroll
            for (int off = 1; off < 16; off <<= 1)
#pragma unroll
                for (int i = 0; i < 4; i++)
                    ts[i] += __shfl_xor_sync(0xffffffffu, ts[i], off);
#pragma unroll
            for (int i = 0; i < 4; i++)
                l[i] = l[i] * alpha[i] + ts[i];

#pragma unroll
            for (int i = 0; i < 4; i++)
#pragma unroll
                for (int j = 0; j < 4; j++)
                    Ps[(sr * 4 + i) * PSTR + sc + 16 * j] = s4[i][j];
            __syncthreads();

#pragma unroll
            for (int i = 0; i < 4; i++) {
                o[i][0] *= alpha[i]; o[i][1] *= alpha[i];
                o[i][2] *= alpha[i]; o[i][3] *= alpha[i];
            }
#pragma unroll 4
            for (int j = 0; j < 64; j++) {
                float p[4];
#pragma unroll
                for (int i = 0; i < 4; i++) p[i] = Ps[(sr * 4 + i) * PSTR + j];
                float4 v = Vs[j * VSTR4 + sc];
#pragma unroll
                for (int i = 0; i < 4; i++) {
                    o[i][0] = fmaf(p[i], v.x, o[i][0]);
                    o[i][1] = fmaf(p[i], v.y, o[i][1]);
                    o[i][2] = fmaf(p[i], v.z, o[i][2]);
                    o[i][3] = fmaf(p[i], v.w, o[i][3]);
                }
            }
            __syncthreads();
        }

#pragma unroll
        for (int i = 0; i < 4; i++) {
            float linv = 1.0f / l[i];
            float4 v = make_float4(o[i][0] * linv, o[i][1] * linv,
                                   o[i][2] * linv, o[i][3] * linv);
            ((float4*)(Out + ((size_t)b * TT + q0 + sr * 4 + i) * HH))[sc] = v;
        }
        __syncthreads();
    }
}

// ---------------------------------------------------------------------------
extern "C" void kernel_launch(void* const* d_in, const int* in_sizes, int n_in,
                              void* d_out, int out_size)
{
    const float* x  = (const float*)d_in[0];
    const float* Wq = (const float*)d_in[1];
    const float* Wk = (const float*)d_in[2];
    const float* Wv = (const float*)d_in[3];
    float* out = (float*)d_out;

    cudaFuncSetAttribute(qkv_mma_kernel,
                         cudaFuncAttributeMaxDynamicSharedMemorySize, QS_TOTAL);
    const size_t attn_smem =
        (size_t)(64 * QSTR4 * 4 + 64 * KSTR4 * 4 + 64 * PSTR + 64 * VSTR4 * 4)
        * sizeof(float);
    cudaFuncSetAttribute(attn_kernel,
                         cudaFuncAttributeMaxDynamicSharedMemorySize, (int)attn_smem);

    wprep_kernel<<<192, 256>>>(Wq, Wk, Wv);
    qkv_mma_kernel<<<MTOT / 128, 256, QS_TOTAL>>>(x);
    attn_kernel<<<dim3(16, BB), 256, attn_smem>>>(out);
}

// round 5
// speedup vs baseline: 3.9324x; 1.8332x over previous
#include <cuda_runtime.h>
#include <cuda_bf16.h>
#include <cstdint>

// Problem constants
#define BB   8
#define TT   2048
#define DD   1024
#define HH   64
#define MTOT (BB * TT)   // 16384

// Scratch: Q,K,V fp32 (12MB) + split-precision transposed weights (768KB)
__device__ float g_qkv[3ull * MTOT * HH];
__device__ __nv_bfloat16 g_WtH[192 * 1024];
__device__ __nv_bfloat16 g_WtL[192 * 1024];

// ===========================================================================
// Helpers (plain sm_100-compatible: mma.sync + cp.async + ldmatrix)
// ===========================================================================
__device__ __forceinline__ uint32_t smem_u32(const void* p) {
    uint32_t a;
    asm("{ .reg .u64 t; cvta.to.shared.u64 t, %1; cvt.u32.u64 %0, t; }"
        : "=r"(a) : "l"(p));
    return a;
}
#define CP_ASYNC16(dst, src) \
    asm volatile("cp.async.cg.shared.global [%0], [%1], 16;" \
                 :: "r"(dst), "l"(src) : "memory")
#define CP_COMMIT() asm volatile("cp.async.commit_group;" ::: "memory")
#define CP_WAIT1()  asm volatile("cp.async.wait_group 1;" ::: "memory")
#define CP_WAIT0()  asm volatile("cp.async.wait_group 0;" ::: "memory")

// split one float2 into packed bf16x2 hi and residual-lo fragments
__device__ __forceinline__ void split2(float2 f, uint32_t& hi, uint32_t& lo) {
    uint32_t h;
    asm("cvt.rn.bf16x2.f32 %0, %1, %2;" : "=r"(h) : "f"(f.y), "f"(f.x));
    float hf0 = __uint_as_float(h << 16);
    float hf1 = __uint_as_float(h & 0xffff0000u);
    float l0 = f.x - hf0;
    float l1 = f.y - hf1;
    asm("cvt.rn.bf16x2.f32 %0, %1, %2;" : "=r"(lo) : "f"(l1), "f"(l0));
    hi = h;
}

__device__ __forceinline__ void mma16816(float* c, const uint32_t* a, uint2 b) {
    asm volatile(
        "mma.sync.aligned.m16n8k16.row.col.f32.bf16.bf16.f32 "
        "{%0,%1,%2,%3}, {%4,%5,%6,%7}, {%8,%9}, {%0,%1,%2,%3};"
        : "+f"(c[0]), "+f"(c[1]), "+f"(c[2]), "+f"(c[3])
        : "r"(a[0]), "r"(a[1]), "r"(a[2]), "r"(a[3]), "r"(b.x), "r"(b.y));
}

__device__ __forceinline__ void ldmx4t(uint32_t* r, uint32_t addr) {
    asm volatile("ldmatrix.sync.aligned.m8n8.x4.trans.shared.b16 "
                 "{%0,%1,%2,%3}, [%4];"
                 : "=r"(r[0]), "=r"(r[1]), "=r"(r[2]), "=r"(r[3]) : "r"(addr));
}

// ===========================================================================
// Kernel 0: W prep (unchanged, passing).
// ===========================================================================
__global__ __launch_bounds__(256) void wprep_kernel(
    const float* __restrict__ Wq,
    const float* __restrict__ Wk,
    const float* __restrict__ Wv)
{
    const int n = blockIdx.x;                 // 0..191
    const float* W = (n < 64) ? Wq : ((n < 128) ? Wk : Wv);
    const int nn = n & 63;
    for (int k = threadIdx.x; k < 1024; k += 256) {
        float w = W[(size_t)k * 64 + nn];
        __nv_bfloat16 h = __float2bfloat16(w);
        float r = w - __bfloat162float(h);
        int p   = (k & 15) >> 1;
        int pos = (k & ~15) + (p & 3) * 4 + (p >> 2) * 2 + (k & 1);
        g_WtH[(size_t)n * 1024 + pos] = h;
        g_WtL[(size_t)n * 1024 + pos] = __float2bfloat16(r);
    }
}

// ===========================================================================
// Kernel 1: QKV projection via mma.sync bf16 split precision (unchanged).
// ===========================================================================
#define XS_STRIDE 272
#define WS_STRIDE 144
#define XS_BYTES  (128 * XS_STRIDE)
#define WS_BYTES  (192 * WS_STRIDE)
#define QS_STAGE  (XS_BYTES + 2 * WS_BYTES)
#define QS_TOTAL  (2 * QS_STAGE)

__global__ __launch_bounds__(256, 1) void qkv_mma_kernel(const float* __restrict__ X)
{
    extern __shared__ char smem[];
    const uint32_t sb = smem_u32(smem);
    const int tid  = threadIdx.x;
    const int wid  = tid >> 5;
    const int lane = tid & 31;
    const int gid  = lane >> 2;
    const int tq   = lane & 3;
    const int wm   = (wid & 3) * 32;
    const int wn   = (wid >> 2) * 96;

    const char* Xg = (const char*)(X + (size_t)blockIdx.x * 128 * DD);
    const char* WHg = (const char*)g_WtH;
    const char* WLg = (const char*)g_WtL;

    auto issue = [&](int c, int s) {
        const uint32_t st = sb + s * QS_STAGE;
        const char* xs = Xg + c * 256;
#pragma unroll
        for (int i = 0; i < 8; i++) {
            int u = tid + 256 * i;
            int r = u >> 4, col = u & 15;
            CP_ASYNC16(st + r * XS_STRIDE + col * 16, xs + (size_t)r * 4096 + col * 16);
        }
        const uint32_t wh = st + XS_BYTES;
        const uint32_t wl = wh + WS_BYTES;
        const char* whs = WHg + c * 128;
        const char* wls = WLg + c * 128;
#pragma unroll
        for (int i = 0; i < 6; i++) {
            int u = tid + 256 * i;
            int n = u >> 3, col = u & 7;
            CP_ASYNC16(wh + n * WS_STRIDE + col * 16, whs + (size_t)n * 2048 + col * 16);
            CP_ASYNC16(wl + n * WS_STRIDE + col * 16, wls + (size_t)n * 2048 + col * 16);
        }
        CP_COMMIT();
    };

    float acc[2][12][4];
#pragma unroll
    for (int m = 0; m < 2; m++)
#pragma unroll
        for (int j = 0; j < 12; j++) {
            acc[m][j][0] = 0.f; acc[m][j][1] = 0.f;
            acc[m][j][2] = 0.f; acc[m][j][3] = 0.f;
        }

    issue(0, 0);

    for (int c = 0; c < 16; c++) {
        const int s = c & 1;
        if (c < 15) { issue(c + 1, s ^ 1); CP_WAIT1(); }
        else        { CP_WAIT0(); }
        __syncthreads();

        const char* Xs = smem + s * QS_STAGE;
        const char* Wh = Xs + XS_BYTES;
        const char* Wl = Wh + WS_BYTES;

#pragma unroll
        for (int ks = 0; ks < 4; ks++) {
            uint32_t Ah[2][4], Al[2][4];
#pragma unroll
            for (int m = 0; m < 2; m++) {
                const int r0 = wm + m * 16 + gid;
                const char* base = Xs + (size_t)r0 * XS_STRIDE + ks * 64 + tq * 8;
                float2 f0 = *(const float2*)(base);
                float2 f1 = *(const float2*)(base + 8 * XS_STRIDE);
                float2 f2 = *(const float2*)(base + 32);
                float2 f3 = *(const float2*)(base + 8 * XS_STRIDE + 32);
                split2(f0, Ah[m][0], Al[m][0]);
                split2(f1, Ah[m][1], Al[m][1]);
                split2(f2, Ah[m][2], Al[m][2]);
                split2(f3, Ah[m][3], Al[m][3]);
            }
#pragma unroll
            for (int j = 0; j < 12; j++) {
                const size_t boff = (size_t)(wn + j * 8 + gid) * WS_STRIDE + ks * 32 + tq * 8;
                uint2 bh = *(const uint2*)(Wh + boff);
                uint2 bl = *(const uint2*)(Wl + boff);
#pragma unroll
                for (int m = 0; m < 2; m++) {
                    mma16816(acc[m][j], Ah[m], bh);
                    mma16816(acc[m][j], Ah[m], bl);
                    mma16816(acc[m][j], Al[m], bh);
                }
            }
        }
        __syncthreads();
    }

#pragma unroll
    for (int m = 0; m < 2; m++) {
        const size_t row = (size_t)blockIdx.x * 128 + wm + m * 16 + gid;
#pragma unroll
        for (int j = 0; j < 12; j++) {
            const int nc = wn + j * 8 + tq * 2;
            const int g  = nc >> 6;
            const int cc = nc & 63;
            float* Cg = g_qkv + (size_t)g * MTOT * HH;
            *(float2*)(Cg + row * HH + cc) =
                make_float2(acc[m][j][0], acc[m][j][1]);
            *(float2*)(Cg + (row + 8) * HH + cc) =
                make_float2(acc[m][j][2], acc[m][j][3]);
        }
    }
}

// ===========================================================================
// Kernel 2: flash attention (causal) via mma.sync bf16 split precision.
// q-tile 64, kv-tile 64, pairing {g, 31-g} -> 33 iters/block, 128 blocks.
// Warp (ch = wid>>2, rg = wid&3): 16 q-rows x 32 kv-cols; O halves reduced
// through smem at epilogue. P never leaves registers.
// ===========================================================================
#define ASTR   144          // bf16 tile row stride in bytes (64*2 + 16 pad)
#define SM_QH  0
#define SM_QL  9216
#define SM_KH  18432
#define SM_KL  27648
#define SM_VH  36864
#define SM_VL  46080
#define SM_RA  55296        // float[2][64]
#define SM_RB  55808        // float[2][64]
#define SM_OB  18432        // epilogue O buffer (overlaps K), stride 68 floats
#define ATTN_SMEM 56320

// convert 16 fp32 (one row segment) into hi/lo bf16 tiles in smem
__device__ __forceinline__ void build16(const float* src, char* dh, char* dl,
                                        float scale) {
    uint32_t H[8], L[8];
#pragma unroll
    for (int q = 0; q < 4; q++) {
        float4 v = ((const float4*)src)[q];
        v.x *= scale; v.y *= scale; v.z *= scale; v.w *= scale;
        split2(make_float2(v.x, v.y), H[2 * q],     L[2 * q]);
        split2(make_float2(v.z, v.w), H[2 * q + 1], L[2 * q + 1]);
    }
    ((uint4*)dh)[0] = make_uint4(H[0], H[1], H[2], H[3]);
    ((uint4*)dh)[1] = make_uint4(H[4], H[5], H[6], H[7]);
    ((uint4*)dl)[0] = make_uint4(L[0], L[1], L[2], L[3]);
    ((uint4*)dl)[1] = make_uint4(L[4], L[5], L[6], L[7]);
}

__global__ __launch_bounds__(256, 1) void attn_kernel(float* __restrict__ Out)
{
    extern __shared__ char smem[];
    const uint32_t sb = smem_u32(smem);

    const int b = blockIdx.y;
    const int g = blockIdx.x;
    const int tid  = threadIdx.x;
    const int wid  = tid >> 5;
    const int lane = tid & 31;
    const int ch   = wid >> 2;     // kv col half (0: 0-31, 1: 32-63)
    const int rg   = wid & 3;      // q row group (16 rows)
    const int gid  = lane >> 2;
    const int tq   = lane & 3;

    const float* Qg = g_qkv + (size_t)b * TT * HH;
    const float* Kg = g_qkv + (size_t)MTOT * HH + (size_t)b * TT * HH;
    const float* Vg = g_qkv + 2ull * MTOT * HH + (size_t)b * TT * HH;

    float* redA = (float*)(smem + SM_RA);
    float* redB = (float*)(smem + SM_RB);

    const int brow = tid >> 2;          // build: row 0..63
    const int bh0  = (tid & 3) * 16;    // build: 16-elem h segment

    const int r0 = 16 * rg + gid;       // this thread's q rows (local)
    const int r1 = r0 + 8;

    for (int pi = 0; pi < 2; pi++) {
        const int qt = pi ? (31 - g) : g;
        const int q0 = qt * 64;

        // ---- build Q (scaled by 1/8, split hi/lo) ----
        build16(Qg + (size_t)(q0 + brow) * HH + bh0,
                smem + SM_QH + brow * ASTR + bh0 * 2,
                smem + SM_QL + brow * ASTR + bh0 * 2, 0.125f);

        float m0 = -1e30f, m1 = -1e30f, l0 = 0.f, l1 = 0.f;
        float oacc[8][4];
#pragma unroll
        for (int j = 0; j < 8; j++) {
            oacc[j][0] = 0.f; oacc[j][1] = 0.f; oacc[j][2] = 0.f; oacc[j][3] = 0.f;
        }
        __syncthreads();

        for (int kt = 0; kt <= qt; kt++) {
            const int k0 = kt * 64;
            // ---- build K, V split tiles ----
            build16(Kg + (size_t)(k0 + brow) * HH + bh0,
                    smem + SM_KH + brow * ASTR + bh0 * 2,
                    smem + SM_KL + brow * ASTR + bh0 * 2, 1.0f);
            build16(Vg + (size_t)(k0 + brow) * HH + bh0,
                    smem + SM_VH + brow * ASTR + bh0 * 2,
                    smem + SM_VL + brow * ASTR + bh0 * 2, 1.0f);
            __syncthreads();

            // ---- S = Q @ K^T (split bf16, fp32 accum) ----
            float sacc[4][4];
#pragma unroll
            for (int j = 0; j < 4; j++) {
                sacc[j][0] = 0.f; sacc[j][1] = 0.f; sacc[j][2] = 0.f; sacc[j][3] = 0.f;
            }
            {
                const char* qh = smem + SM_QH + r0 * ASTR + tq * 4;
                const char* ql = smem + SM_QL + r0 * ASTR + tq * 4;
                const char* kh = smem + SM_KH + (32 * ch + gid) * ASTR + tq * 4;
                const char* kl = smem + SM_KL + (32 * ch + gid) * ASTR + tq * 4;
#pragma unroll
                for (int kb = 0; kb < 4; kb++) {
                    uint32_t Ah[4], Al[4];
                    Ah[0] = *(const uint32_t*)(qh + kb * 32);
                    Ah[1] = *(const uint32_t*)(qh + 8 * ASTR + kb * 32);
                    Ah[2] = *(const uint32_t*)(qh + kb * 32 + 16);
                    Ah[3] = *(const uint32_t*)(qh + 8 * ASTR + kb * 32 + 16);
                    Al[0] = *(const uint32_t*)(ql + kb * 32);
                    Al[1] = *(const uint32_t*)(ql + 8 * ASTR + kb * 32);
                    Al[2] = *(const uint32_t*)(ql + kb * 32 + 16);
                    Al[3] = *(const uint32_t*)(ql + 8 * ASTR + kb * 32 + 16);
#pragma unroll
                    for (int j = 0; j < 4; j++) {
                        uint2 bh, bl;
                        bh.x = *(const uint32_t*)(kh + j * 8 * ASTR + kb * 32);
                        bh.y = *(const uint32_t*)(kh + j * 8 * ASTR + kb * 32 + 16);
                        bl.x = *(const uint32_t*)(kl + j * 8 * ASTR + kb * 32);
                        bl.y = *(const uint32_t*)(kl + j * 8 * ASTR + kb * 32 + 16);
                        mma16816(sacc[j], Ah, bh);
                        mma16816(sacc[j], Ah, bl);
                        mma16816(sacc[j], Al, bh);
                    }
                }
            }

            // ---- causal mask + partial row max ----
            const bool diag = (kt == qt);
            float mx0 = -1e30f, mx1 = -1e30f;
#pragma unroll
            for (int j = 0; j < 4; j++) {
                const int c0 = 32 * ch + 8 * j + 2 * tq;
                if (diag) {
                    if (c0     > r0) sacc[j][0] = -1e30f;
                    if (c0 + 1 > r0) sacc[j][1] = -1e30f;
                    if (c0     > r1) sacc[j][2] = -1e30f;
                    if (c0 + 1 > r1) sacc[j][3] = -1e30f;
                }
                mx0 = fmaxf(mx0, fmaxf(sacc[j][0], sacc[j][1]));
                mx1 = fmaxf(mx1, fmaxf(sacc[j][2], sacc[j][3]));
            }
            mx0 = fmaxf(mx0, __shfl_xor_sync(0xffffffffu, mx0, 1));
            mx0 = fmaxf(mx0, __shfl_xor_sync(0xffffffffu, mx0, 2));
            mx1 = fmaxf(mx1, __shfl_xor_sync(0xffffffffu, mx1, 1));
            mx1 = fmaxf(mx1, __shfl_xor_sync(0xffffffffu, mx1, 2));
            if (tq == 0) {
                redA[ch * 64 + r0] = mx0;
                redA[ch * 64 + r1] = mx1;
            }
            __syncthreads();

            // ---- full row max, exp, partial sums ----
            const float om0 = m0, om1 = m1;
            m0 = fmaxf(m0, fmaxf(redA[r0], redA[64 + r0]));
            m1 = fmaxf(m1, fmaxf(redA[r1], redA[64 + r1]));
            const float al0 = __expf(om0 - m0);
            const float al1 = __expf(om1 - m1);
            float s0 = 0.f, s1 = 0.f;
#pragma unroll
            for (int j = 0; j < 4; j++) {
                sacc[j][0] = __expf(sacc[j][0] - m0);
                sacc[j][1] = __expf(sacc[j][1] - m0);
                sacc[j][2] = __expf(sacc[j][2] - m1);
                sacc[j][3] = __expf(sacc[j][3] - m1);
                s0 += sacc[j][0] + sacc[j][1];
                s1 += sacc[j][2] + sacc[j][3];
            }
            s0 += __shfl_xor_sync(0xffffffffu, s0, 1);
            s0 += __shfl_xor_sync(0xffffffffu, s0, 2);
            s1 += __shfl_xor_sync(0xffffffffu, s1, 1);
            s1 += __shfl_xor_sync(0xffffffffu, s1, 2);
            if (tq == 0) {
                redB[ch * 64 + r0] = s0;
                redB[ch * 64 + r1] = s1;
            }

            // ---- split P to bf16 hi/lo (registers only) ----
            uint32_t ph[4], pl[4], ph2[4], pl2[4];
#pragma unroll
            for (int j = 0; j < 4; j++) {
                split2(make_float2(sacc[j][0], sacc[j][1]), ph[j],  pl[j]);
                split2(make_float2(sacc[j][2], sacc[j][3]), ph2[j], pl2[j]);
            }

            // ---- rescale O, then O += P @ V ----
#pragma unroll
            for (int j = 0; j < 8; j++) {
                oacc[j][0] *= al0; oacc[j][1] *= al0;
                oacc[j][2] *= al1; oacc[j][3] *= al1;
            }
            const int lrow = (lane & 7) + ((lane >> 3) & 1) * 8;
            const int lcol = (lane >> 4) * 8;
#pragma unroll
            for (int kb = 0; kb < 2; kb++) {
                uint32_t Aph[4] = {ph[2 * kb], ph2[2 * kb], ph[2 * kb + 1], ph2[2 * kb + 1]};
                uint32_t Apl[4] = {pl[2 * kb], pl2[2 * kb], pl[2 * kb + 1], pl2[2 * kb + 1]};
                const uint32_t vrow = (32 * ch + 16 * kb + lrow) * ASTR;
#pragma unroll
                for (int jj = 0; jj < 4; jj++) {
                    uint32_t vh[4], vl[4];
                    const uint32_t coff = (16 * jj + lcol) * 2;
                    ldmx4t(vh, sb + SM_VH + vrow + coff);
                    ldmx4t(vl, sb + SM_VL + vrow + coff);
                    mma16816(oacc[2 * jj],     Aph, make_uint2(vh[0], vh[1]));
                    mma16816(oacc[2 * jj + 1], Aph, make_uint2(vh[2], vh[3]));
                    mma16816(oacc[2 * jj],     Aph, make_uint2(vl[0], vl[1]));
                    mma16816(oacc[2 * jj + 1], Aph, make_uint2(vl[2], vl[3]));
                    mma16816(oacc[2 * jj],     Apl, make_uint2(vh[0], vh[1]));
                    mma16816(oacc[2 * jj + 1], Apl, make_uint2(vh[2], vh[3]));
                }
            }
            __syncthreads();

            l0 = l0 * al0 + redB[r0] + redB[64 + r0];
            l1 = l1 * al1 + redB[r1] + redB[64 + r1];
        }

        // ---- epilogue: reduce O halves across warp pairs, normalize, store ----
        float* ob = (float*)(smem + SM_OB);
        if (ch == 1) {
#pragma unroll
            for (int j = 0; j < 8; j++) {
                *(float2*)(ob + r0 * 68 + 8 * j + 2 * tq) =
                    make_float2(oacc[j][0], oacc[j][1]);
                *(float2*)(ob + r1 * 68 + 8 * j + 2 * tq) =
                    make_float2(oacc[j][2], oacc[j][3]);
            }
        }
        __syncthreads();
        if (ch == 0) {
            const float inv0 = 1.0f / l0;
            const float inv1 = 1.0f / l1;
            float* out0 = Out + ((size_t)b * TT + q0 + r0) * HH;
            float* out1 = Out + ((size_t)b * TT + q0 + r1) * HH;
#pragma unroll
            for (int j = 0; j < 8; j++) {
                float2 p0 = *(float2*)(ob + r0 * 68 + 8 * j + 2 * tq);
                float2 p1 = *(float2*)(ob + r1 * 68 + 8 * j + 2 * tq);
                *(float2*)(out0 + 8 * j + 2 * tq) =
                    make_float2((oacc[j][0] + p0.x) * inv0, (oacc[j][1] + p0.y) * inv0);
                *(float2*)(out1 + 8 * j + 2 * tq) =
                    make_float2((oacc[j][2] + p1.x) * inv1, (oacc[j][3] + p1.y) * inv1);
            }
        }
        __syncthreads();
    }
}

// ---------------------------------------------------------------------------
extern "C" void kernel_launch(void* const* d_in, const int* in_sizes, int n_in,
                              void* d_out, int out_size)
{
    const float* x  = (const float*)d_in[0];
    const float* Wq = (const float*)d_in[1];
    const float* Wk = (const float*)d_in[2];
    const float* Wv = (const float*)d_in[3];
    float* out = (float*)d_out;

    cudaFuncSetAttribute(qkv_mma_kernel,
                         cudaFuncAttributeMaxDynamicSharedMemorySize, QS_TOTAL);
    cudaFuncSetAttribute(attn_kernel,
                         cudaFuncAttributeMaxDynamicSharedMemorySize, ATTN_SMEM);

    wprep_kernel<<<192, 256>>>(Wq, Wk, Wv);
    qkv_mma_kernel<<<MTOT / 128, 256, QS_TOTAL>>>(x);
    attn_kernel<<<dim3(16, BB), 256, ATTN_SMEM>>>(out);
}

// round 7
// speedup vs baseline: 4.3484x; 1.1058x over previous
#include <cuda_runtime.h>
#include <cuda_bf16.h>
#include <cstdint>

// Problem constants
#define BB   8
#define TT   2048
#define DD   1024
#define HH   64
#define MTOT (BB * TT)   // 16384

// Pre-split (hi/lo bf16) Q,K,V produced by the projection kernel. Q pre-scaled 1/8.
__device__ __nv_bfloat16 g_qH[(size_t)MTOT * HH];
__device__ __nv_bfloat16 g_qL[(size_t)MTOT * HH];
__device__ __nv_bfloat16 g_kH[(size_t)MTOT * HH];
__device__ __nv_bfloat16 g_kL[(size_t)MTOT * HH];
__device__ __nv_bfloat16 g_vH[(size_t)MTOT * HH];
__device__ __nv_bfloat16 g_vL[(size_t)MTOT * HH];
// Split-precision transposed weights
__device__ __nv_bfloat16 g_WtH[192 * 1024];
__device__ __nv_bfloat16 g_WtL[192 * 1024];

// ===========================================================================
// Helpers (plain sm_100-compatible: mma.sync + cp.async + ldmatrix)
// ===========================================================================
__device__ __forceinline__ uint32_t smem_u32(const void* p) {
    uint32_t a;
    asm("{ .reg .u64 t; cvta.to.shared.u64 t, %1; cvt.u32.u64 %0, t; }"
        : "=r"(a) : "l"(p));
    return a;
}
#define CP_ASYNC16(dst, src) \
    asm volatile("cp.async.cg.shared.global [%0], [%1], 16;" \
                 :: "r"(dst), "l"(src) : "memory")
#define CP_COMMIT() asm volatile("cp.async.commit_group;" ::: "memory")
#define CP_WAIT1()  asm volatile("cp.async.wait_group 1;" ::: "memory")
#define CP_WAIT0()  asm volatile("cp.async.wait_group 0;" ::: "memory")

// split one float2 into packed bf16x2 hi and residual-lo fragments
__device__ __forceinline__ void split2(float2 f, uint32_t& hi, uint32_t& lo) {
    uint32_t h;
    asm("cvt.rn.bf16x2.f32 %0, %1, %2;" : "=r"(h) : "f"(f.y), "f"(f.x));
    float hf0 = __uint_as_float(h << 16);
    float hf1 = __uint_as_float(h & 0xffff0000u);
    float l0 = f.x - hf0;
    float l1 = f.y - hf1;
    asm("cvt.rn.bf16x2.f32 %0, %1, %2;" : "=r"(lo) : "f"(l1), "f"(l0));
    hi = h;
}

__device__ __forceinline__ void mma16816(float* c, const uint32_t* a, uint2 b) {
    asm volatile(
        "mma.sync.aligned.m16n8k16.row.col.f32.bf16.bf16.f32 "
        "{%0,%1,%2,%3}, {%4,%5,%6,%7}, {%8,%9}, {%0,%1,%2,%3};"
        : "+f"(c[0]), "+f"(c[1]), "+f"(c[2]), "+f"(c[3])
        : "r"(a[0]), "r"(a[1]), "r"(a[2]), "r"(a[3]), "r"(b.x), "r"(b.y));
}

__device__ __forceinline__ void ldmx4t(uint32_t* r, uint32_t addr) {
    asm volatile("ldmatrix.sync.aligned.m8n8.x4.trans.shared.b16 "
                 "{%0,%1,%2,%3}, [%4];"
                 : "=r"(r[0]), "=r"(r[1]), "=r"(r[2]), "=r"(r[3]) : "r"(addr));
}

// ===========================================================================
// Kernel 0: W prep (unchanged, passing).
// ===========================================================================
__global__ __launch_bounds__(256) void wprep_kernel(
    const float* __restrict__ Wq,
    const float* __restrict__ Wk,
    const float* __restrict__ Wv)
{
    const int n = blockIdx.x;                 // 0..191
    const float* W = (n < 64) ? Wq : ((n < 128) ? Wk : Wv);
    const int nn = n & 63;
    for (int k = threadIdx.x; k < 1024; k += 256) {
        float w = W[(size_t)k * 64 + nn];
        __nv_bfloat16 h = __float2bfloat16(w);
        float r = w - __bfloat162float(h);
        int p   = (k & 15) >> 1;
        int pos = (k & ~15) + (p & 3) * 4 + (p >> 2) * 2 + (k & 1);
        g_WtH[(size_t)n * 1024 + pos] = h;
        g_WtL[(size_t)n * 1024 + pos] = __float2bfloat16(r);
    }
}

// ===========================================================================
// Kernel 1: QKV projection via mma.sync bf16 split precision.
// Mainloop unchanged; epilogue emits pre-split hi/lo bf16 (Q scaled 1/8).
// ===========================================================================
#define XS_STRIDE 272
#define WS_STRIDE 144
#define XS_BYTES  (128 * XS_STRIDE)
#define WS_BYTES  (192 * WS_STRIDE)
#define QS_STAGE  (XS_BYTES + 2 * WS_BYTES)
#define QS_TOTAL  (2 * QS_STAGE)

__global__ __launch_bounds__(256, 1) void qkv_mma_kernel(const float* __restrict__ X)
{
    extern __shared__ char smem[];
    const uint32_t sb = smem_u32(smem);
    const int tid  = threadIdx.x;
    const int wid  = tid >> 5;
    const int lane = tid & 31;
    const int gid  = lane >> 2;
    const int tq   = lane & 3;
    const int wm   = (wid & 3) * 32;
    const int wn   = (wid >> 2) * 96;

    const char* Xg = (const char*)(X + (size_t)blockIdx.x * 128 * DD);
    const char* WHg = (const char*)g_WtH;
    const char* WLg = (const char*)g_WtL;

    auto issue = [&](int c, int s) {
        const uint32_t st = sb + s * QS_STAGE;
        const char* xs = Xg + c * 256;
#pragma unroll
        for (int i = 0; i < 8; i++) {
            int u = tid + 256 * i;
            int r = u >> 4, col = u & 15;
            CP_ASYNC16(st + r * XS_STRIDE + col * 16, xs + (size_t)r * 4096 + col * 16);
        }
        const uint32_t wh = st + XS_BYTES;
        const uint32_t wl = wh + WS_BYTES;
        const char* whs = WHg + c * 128;
        const char* wls = WLg + c * 128;
#pragma unroll
        for (int i = 0; i < 6; i++) {
            int u = tid + 256 * i;
            int n = u >> 3, col = u & 7;
            CP_ASYNC16(wh + n * WS_STRIDE + col * 16, whs + (size_t)n * 2048 + col * 16);
            CP_ASYNC16(wl + n * WS_STRIDE + col * 16, wls + (size_t)n * 2048 + col * 16);
        }
        CP_COMMIT();
    };

    float acc[2][12][4];
#pragma unroll
    for (int m = 0; m < 2; m++)
#pragma unroll
        for (int j = 0; j < 12; j++) {
            acc[m][j][0] = 0.f; acc[m][j][1] = 0.f;
            acc[m][j][2] = 0.f; acc[m][j][3] = 0.f;
        }

    issue(0, 0);

    for (int c = 0; c < 16; c++) {
        const int s = c & 1;
        if (c < 15) { issue(c + 1, s ^ 1); CP_WAIT1(); }
        else        { CP_WAIT0(); }
        __syncthreads();

        const char* Xs = smem + s * QS_STAGE;
        const char* Wh = Xs + XS_BYTES;
        const char* Wl = Wh + WS_BYTES;

#pragma unroll
        for (int ks = 0; ks < 4; ks++) {
            uint32_t Ah[2][4], Al[2][4];
#pragma unroll
            for (int m = 0; m < 2; m++) {
                const int r0 = wm + m * 16 + gid;
                const char* base = Xs + (size_t)r0 * XS_STRIDE + ks * 64 + tq * 8;
                float2 f0 = *(const float2*)(base);
                float2 f1 = *(const float2*)(base + 8 * XS_STRIDE);
                float2 f2 = *(const float2*)(base + 32);
                float2 f3 = *(const float2*)(base + 8 * XS_STRIDE + 32);
                split2(f0, Ah[m][0], Al[m][0]);
                split2(f1, Ah[m][1], Al[m][1]);
                split2(f2, Ah[m][2], Al[m][2]);
                split2(f3, Ah[m][3], Al[m][3]);
            }
#pragma unroll
            for (int j = 0; j < 12; j++) {
                const size_t boff = (size_t)(wn + j * 8 + gid) * WS_STRIDE + ks * 32 + tq * 8;
                uint2 bh = *(const uint2*)(Wh + boff);
                uint2 bl = *(const uint2*)(Wl + boff);
#pragma unroll
                for (int m = 0; m < 2; m++) {
                    mma16816(acc[m][j], Ah[m], bh);
                    mma16816(acc[m][j], Ah[m], bl);
                    mma16816(acc[m][j], Al[m], bh);
                }
            }
        }
        __syncthreads();
    }

    // ---- epilogue: split to hi/lo bf16 and store (Q pre-scaled by 1/8) ----
#pragma unroll
    for (int m = 0; m < 2; m++) {
        const size_t row = (size_t)blockIdx.x * 128 + wm + m * 16 + gid;
#pragma unroll
        for (int j = 0; j < 12; j++) {
            const int nc = wn + j * 8 + tq * 2;
            const int g  = nc >> 6;
            const int cc = nc & 63;
            const float sc = (g == 0) ? 0.125f : 1.0f;
            __nv_bfloat16* H = (g == 0) ? g_qH : ((g == 1) ? g_kH : g_vH);
            __nv_bfloat16* L = (g == 0) ? g_qL : ((g == 1) ? g_kL : g_vL);
            uint32_t h0, l0, h1, l1;
            split2(make_float2(acc[m][j][0] * sc, acc[m][j][1] * sc), h0, l0);
            split2(make_float2(acc[m][j][2] * sc, acc[m][j][3] * sc), h1, l1);
            *(uint32_t*)((char*)H + (row * HH + cc) * 2)       = h0;
            *(uint32_t*)((char*)L + (row * HH + cc) * 2)       = l0;
            *(uint32_t*)((char*)H + ((row + 8) * HH + cc) * 2) = h1;
            *(uint32_t*)((char*)L + ((row + 8) * HH + cc) * 2) = l1;
        }
    }
}

// ===========================================================================
// Kernel 2: flash attention (causal) via mma.sync bf16 split precision.
// Consumes pre-split Q/K/V; K/V double-buffered with cp.async.
// q-tile 64, kv-tile 64, pairing {g, 31-g} -> 33 iters/block, 128 blocks.
// ===========================================================================
#define ASTR      144        // smem tile row stride (64*2 bf16 + 16 pad)
#define SM_QH     0
#define SM_QL     9216
#define SM_KV     18432
#define KV_STAGE  36864      // KH, KL, VH, VL at +0, +9216, +18432, +27648
#define SM_RA     92160      // float[2][64]
#define SM_RB     92672      // float[2][64]
#define SM_OB     18432      // epilogue O buffer (overlaps KV stage 0)
#define ATTN_SMEM 93184

__global__ __launch_bounds__(256, 1) void attn_kernel(float* __restrict__ Out)
{
    extern __shared__ char smem[];
    const uint32_t sb = smem_u32(smem);

    const int b = blockIdx.y;
    const int g = blockIdx.x;
    const int tid  = threadIdx.x;
    const int wid  = tid >> 5;
    const int lane = tid & 31;
    const int ch   = wid >> 2;     // kv col half (0: 0-31, 1: 32-63)
    const int rg   = wid & 3;      // q row group (16 rows)
    const int gid  = lane >> 2;
    const int tq   = lane & 3;

    const size_t boff = (size_t)b * TT * HH * 2;   // byte offset for this batch
    const char* qHg = (const char*)g_qH + boff;
    const char* qLg = (const char*)g_qL + boff;
    const char* kHg = (const char*)g_kH + boff;
    const char* kLg = (const char*)g_kL + boff;
    const char* vHg = (const char*)g_vH + boff;
    const char* vLg = (const char*)g_vL + boff;

    float* redA = (float*)(smem + SM_RA);
    float* redB = (float*)(smem + SM_RB);

    const int r0 = 16 * rg + gid;       // this thread's q rows (local)
    const int r1 = r0 + 8;

    // async loaders -------------------------------------------------------
    auto issue_q = [&](int q0) {
#pragma unroll
        for (int i = 0; i < 4; i++) {
            int u = tid + 256 * i;             // 0..1023
            int t = u >> 9;                    // 0: H, 1: L
            int r = (u >> 3) & 63;
            int cc = u & 7;
            const char* src = (t ? qLg : qHg) + (size_t)(q0 + r) * 128 + cc * 16;
            CP_ASYNC16(sb + SM_QH + t * 9216 + r * ASTR + cc * 16, src);
        }
        CP_COMMIT();
    };
    auto issue_kv = [&](int k0, int s) {
        const uint32_t base = sb + SM_KV + s * KV_STAGE;
#pragma unroll
        for (int i = 0; i < 8; i++) {
            int u = tid + 256 * i;             // 0..2047
            int t = u >> 9;                    // 0..3 -> KH,KL,VH,VL
            int r = (u >> 3) & 63;
            int cc = u & 7;
            const char* src = (t == 0 ? kHg : t == 1 ? kLg : t == 2 ? vHg : vLg)
                              + (size_t)(k0 + r) * 128 + cc * 16;
            CP_ASYNC16(base + t * 9216 + r * ASTR + cc * 16, src);
        }
        CP_COMMIT();
    };

    for (int pi = 0; pi < 2; pi++) {
        const int qt = pi ? (31 - g) : g;
        const int q0 = qt * 64;

        issue_q(q0);
        issue_kv(0, 0);

        float m0 = -1e30f, m1 = -1e30f, l0 = 0.f, l1 = 0.f;
        float oacc[8][4];
#pragma unroll
        for (int j = 0; j < 8; j++) {
            oacc[j][0] = 0.f; oacc[j][1] = 0.f; oacc[j][2] = 0.f; oacc[j][3] = 0.f;
        }

        for (int kt = 0; kt <= qt; kt++) {
            if (kt < qt) { issue_kv((kt + 1) * 64, (kt + 1) & 1); CP_WAIT1(); }
            else         { CP_WAIT0(); }
            __syncthreads();

            const char* st = smem + SM_KV + (kt & 1) * KV_STAGE;

            // ---- S = Q @ K^T (split bf16, fp32 accum) ----
            float sacc[4][4];
#pragma unroll
            for (int j = 0; j < 4; j++) {
                sacc[j][0] = 0.f; sacc[j][1] = 0.f; sacc[j][2] = 0.f; sacc[j][3] = 0.f;
            }
            {
                const char* qh = smem + SM_QH + r0 * ASTR + tq * 4;
                const char* ql = smem + SM_QL + r0 * ASTR + tq * 4;
                const char* kh = st + (32 * ch + gid) * ASTR + tq * 4;
                const char* kl = kh + 9216;
#pragma unroll
                for (int kb = 0; kb < 4; kb++) {
                    uint32_t Ah[4], Al[4];
                    Ah[0] = *(const uint32_t*)(qh + kb * 32);
                    Ah[1] = *(const uint32_t*)(qh + 8 * ASTR + kb * 32);
                    Ah[2] = *(const uint32_t*)(qh + kb * 32 + 16);
                    Ah[3] = *(const uint32_t*)(qh + 8 * ASTR + kb * 32 + 16);
                    Al[0] = *(const uint32_t*)(ql + kb * 32);
                    Al[1] = *(const uint32_t*)(ql + 8 * ASTR + kb * 32);
                    Al[2] = *(const uint32_t*)(ql + kb * 32 + 16);
                    Al[3] = *(const uint32_t*)(ql + 8 * ASTR + kb * 32 + 16);
#pragma unroll
                    for (int j = 0; j < 4; j++) {
                        uint2 bh, bl;
                        bh.x = *(const uint32_t*)(kh + j * 8 * ASTR + kb * 32);
                        bh.y = *(const uint32_t*)(kh + j * 8 * ASTR + kb * 32 + 16);
                        bl.x = *(const uint32_t*)(kl + j * 8 * ASTR + kb * 32);
                        bl.y = *(const uint32_t*)(kl + j * 8 * ASTR + kb * 32 + 16);
                        mma16816(sacc[j], Ah, bh);
                        mma16816(sacc[j], Ah, bl);
                        mma16816(sacc[j], Al, bh);
                    }
                }
            }

            // ---- causal mask + partial row max ----
            const bool diag = (kt == qt);
            float mx0 = -1e30f, mx1 = -1e30f;
#pragma unroll
            for (int j = 0; j < 4; j++) {
                const int c0 = 32 * ch + 8 * j + 2 * tq;
                if (diag) {
                    if (c0     > r0) sacc[j][0] = -1e30f;
                    if (c0 + 1 > r0) sacc[j][1] = -1e30f;
                    if (c0     > r1) sacc[j][2] = -1e30f;
                    if (c0 + 1 > r1) sacc[j][3] = -1e30f;
                }
                mx0 = fmaxf(mx0, fmaxf(sacc[j][0], sacc[j][1]));
                mx1 = fmaxf(mx1, fmaxf(sacc[j][2], sacc[j][3]));
            }
            mx0 = fmaxf(mx0, __shfl_xor_sync(0xffffffffu, mx0, 1));
            mx0 = fmaxf(mx0, __shfl_xor_sync(0xffffffffu, mx0, 2));
            mx1 = fmaxf(mx1, __shfl_xor_sync(0xffffffffu, mx1, 1));
            mx1 = fmaxf(mx1, __shfl_xor_sync(0xffffffffu, mx1, 2));
            if (tq == 0) {
                redA[ch * 64 + r0] = mx0;
                redA[ch * 64 + r1] = mx1;
            }
            __syncthreads();

            // ---- full row max, exp, partial sums ----
            const float om0 = m0, om1 = m1;
            m0 = fmaxf(m0, fmaxf(redA[r0], redA[64 + r0]));
            m1 = fmaxf(m1, fmaxf(redA[r1], redA[64 + r1]));
            const float al0 = __expf(om0 - m0);
            const float al1 = __expf(om1 - m1);
            float s0 = 0.f, s1 = 0.f;
#pragma unroll
            for (int j = 0; j < 4; j++) {
                sacc[j][0] = __expf(sacc[j][0] - m0);
                sacc[j][1] = __expf(sacc[j][1] - m0);
                sacc[j][2] = __expf(sacc[j][2] - m1);
                sacc[j][3] = __expf(sacc[j][3] - m1);
                s0 += sacc[j][0] + sacc[j][1];
                s1 += sacc[j][2] + sacc[j][3];
            }
            s0 += __shfl_xor_sync(0xffffffffu, s0, 1);
            s0 += __shfl_xor_sync(0xffffffffu, s0, 2);
            s1 += __shfl_xor_sync(0xffffffffu, s1, 1);
            s1 += __shfl_xor_sync(0xffffffffu, s1, 2);
            if (tq == 0) {
                redB[ch * 64 + r0] = s0;
                redB[ch * 64 + r1] = s1;
            }

            // ---- split P to bf16 hi/lo (registers only) ----
            uint32_t ph[4], pl[4], ph2[4], pl2[4];
#pragma unroll
            for (int j = 0; j < 4; j++) {
                split2(make_float2(sacc[j][0], sacc[j][1]), ph[j],  pl[j]);
                split2(make_float2(sacc[j][2], sacc[j][3]), ph2[j], pl2[j]);
            }

            // ---- rescale O, then O += P @ V ----
#pragma unroll
            for (int j = 0; j < 8; j++) {
                oacc[j][0] *= al0; oacc[j][1] *= al0;
                oacc[j][2] *= al1; oacc[j][3] *= al1;
            }
            const int lrow = (lane & 7) + ((lane >> 3) & 1) * 8;
            const int lcol = (lane >> 4) * 8;
            const uint32_t vbase = sb + SM_KV + (kt & 1) * KV_STAGE + 18432;
#pragma unroll
            for (int kb = 0; kb < 2; kb++) {
                uint32_t Aph[4] = {ph[2 * kb], ph2[2 * kb], ph[2 * kb + 1], ph2[2 * kb + 1]};
                uint32_t Apl[4] = {pl[2 * kb], pl2[2 * kb], pl[2 * kb + 1], pl2[2 * kb + 1]};
                const uint32_t vrow = (32 * ch + 16 * kb + lrow) * ASTR;
#pragma unroll
                for (int jj = 0; jj < 4; jj++) {
                    uint32_t vh[4], vl[4];
                    const uint32_t coff = (16 * jj + lcol) * 2;
                    ldmx4t(vh, vbase + vrow + coff);
                    ldmx4t(vl, vbase + 9216 + vrow + coff);
                    mma16816(oacc[2 * jj],     Aph, make_uint2(vh[0], vh[1]));
                    mma16816(oacc[2 * jj + 1], Aph, make_uint2(vh[2], vh[3]));
                    mma16816(oacc[2 * jj],     Aph, make_uint2(vl[0], vl[1]));
                    mma16816(oacc[2 * jj + 1], Aph, make_uint2(vl[2], vl[3]));
                    mma16816(oacc[2 * jj],     Apl, make_uint2(vh[0], vh[1]));
                    mma16816(oacc[2 * jj + 1], Apl, make_uint2(vh[2], vh[3]));
                }
            }
            __syncthreads();

            l0 = l0 * al0 + redB[r0] + redB[64 + r0];
            l1 = l1 * al1 + redB[r1] + redB[64 + r1];
        }

        // ---- epilogue: reduce O halves across warp pairs, normalize, store ----
        float* ob = (float*)(smem + SM_OB);
        if (ch == 1) {
#pragma unroll
            for (int j = 0; j < 8; j++) {
                *(float2*)(ob + r0 * 68 + 8 * j + 2 * tq) =
                    make_float2(oacc[j][0], oacc[j][1]);
                *(float2*)(ob + r1 * 68 + 8 * j + 2 * tq) =
                    make_float2(oacc[j][2], oacc[j][3]);
            }
        }
        __syncthreads();
        if (ch == 0) {
            const float inv0 = 1.0f / l0;
            const float inv1 = 1.0f / l1;
            float* out0 = Out + ((size_t)b * TT + q0 + r0) * HH;
            float* out1 = Out + ((size_t)b * TT + q0 + r1) * HH;
#pragma unroll
            for (int j = 0; j < 8; j++) {
                float2 p0 = *(float2*)(ob + r0 * 68 + 8 * j + 2 * tq);
                float2 p1 = *(float2*)(ob + r1 * 68 + 8 * j + 2 * tq);
                *(float2*)(out0 + 8 * j + 2 * tq) =
                    make_float2((oacc[j][0] + p0.x) * inv0, (oacc[j][1] + p0.y) * inv0);
                *(float2*)(out1 + 8 * j + 2 * tq) =
                    make_float2((oacc[j][2] + p1.x) * inv1, (oacc[j][3] + p1.y) * inv1);
            }
        }
        __syncthreads();
    }
}

// ---------------------------------------------------------------------------
extern "C" void kernel_launch(void* const* d_in, const int* in_sizes, int n_in,
                              void* d_out, int out_size)
{
    const float* x  = (const float*)d_in[0];
    const float* Wq = (const float*)d_in[1];
    const float* Wk = (const float*)d_in[2];
    const float* Wv = (const float*)d_in[3];
    float* out = (float*)d_out;

    cudaFuncSetAttribute(qkv_mma_kernel,
                         cudaFuncAttributeMaxDynamicSharedMemorySize, QS_TOTAL);
    cudaFuncSetAttribute(attn_kernel,
                         cudaFuncAttributeMaxDynamicSharedMemorySize, ATTN_SMEM);

    wprep_kernel<<<192, 256>>>(Wq, Wk, Wv);
    qkv_mma_kernel<<<MTOT / 128, 256, QS_TOTAL>>>(x);
    attn_kernel<<<dim3(16, BB), 256, ATTN_SMEM>>>(out);
}